// round 13
// baseline (speedup 1.0000x reference)
#include <cuda_runtime.h>
#include <cuda_bf16.h>
#include <cstddef>
#include <cstdint>

// CompressK: ragged strided chunk mean-pool (NSA K compression).
//   k:          [total_tokens, H, D] fp32   (H*D = 512 here)
//   cu_seqlens: [B+1] int32
//   kernel_size, kernel_stride: int32 scalars (device)
// Output: compressed_k [NC, H, D] fp32 followed by (B+1) compressed
// cu_seqlens as float values.
//
// R12 = the 10.7us winner's structure (G=2 streaming half-sums, 128-thr
// blocks, fused tail, unconditional clamped loads) rebuilt on 256-bit
// loads (ld.global.nc.v8.b32 — confirmed available on sm_103 ptxas).
// Thread t owns an 8-float d-slice of the even (t<64) or odd (t>=64)
// rows of each 1KB two-row pair; per-half partials are 8 batched 32B
// loads (2x the in-flight bytes per scoreboard slot of the float4
// version). One 4KB smem exchange + single __syncthreads at the END
// combines even/odd partials; each thread-half stores one chunk.

#define HD    512          // H * D (floats per row)
#define HD4   (HD / 4)
#define BLK   128
#define G     2            // chunks per block (fast path)
#define KS_C  32
#define ST_C  16

__device__ __forceinline__ void ldg256(const float* p, float* v) {
    asm volatile("ld.global.nc.v8.b32 {%0,%1,%2,%3,%4,%5,%6,%7}, [%8];"
                 : "=f"(v[0]), "=f"(v[1]), "=f"(v[2]), "=f"(v[3]),
                   "=f"(v[4]), "=f"(v[5]), "=f"(v[6]), "=f"(v[7])
                 : "l"(p));
}

// Sum this thread's parity-rows of one 16-row half: 8 pairs x 32B loads.
__device__ __forceinline__ void halfsum_v8(const float* __restrict__ p,
                                           float acc[8]) {
    float v[8][8];
    #pragma unroll
    for (int i = 0; i < 8; i++) ldg256(p + i * 2 * HD, v[i]);
    #pragma unroll
    for (int j = 0; j < 8; j++) {
        acc[j] = ((v[0][j] + v[1][j]) + (v[2][j] + v[3][j]))
               + ((v[4][j] + v[5][j]) + (v[6][j] + v[7][j]));
    }
}

__global__ void __launch_bounds__(BLK)
compressk_kernel(const float*  __restrict__ kf,
                 const int*    __restrict__ cu,
                 const int*    __restrict__ p_ks,
                 const int*    __restrict__ p_st,
                 float*        __restrict__ out,
                 float*        __restrict__ out_tail,
                 int B, int tail_n)
{
    // sh[0][u] = chunk1 even-partial (from t<64); sh[1][u] = chunk0 odd-partial.
    __shared__ float sh[2][64][8];

    const int tid = threadIdx.x;
    const int g   = blockIdx.x;
    const int ks  = __ldg(p_ks);
    const int st  = __ldg(p_st);
    const int T   = __ldg(cu + B);

    // Fused tail: block 0 writes the compressed cu_seqlens.
    if (g == 0 && tid < tail_n) {
        int acc = 0;
        for (int j = 0; j < tid; j++) {
            const int len = __ldg(cu + j + 1) - __ldg(cu + j);
            acc += (len >= ks) ? (len - ks) / st + 1 : 0;
        }
        out_tail[tid] = (float)acc;
    }

    // Locate this block's chunk group via a scan over the (tiny) cu_seqlens.
    int start_tok = 0, chunk0 = 0, gn = 0;
    {
        int gacc = 0, cacc = 0;
        #pragma unroll 4
        for (int i = 0; i < B; i++) {
            const int s0  = __ldg(cu + i);
            const int s1  = __ldg(cu + i + 1);
            const int len = s1 - s0;
            const int nc  = (len >= ks) ? (len - ks) / st + 1 : 0;
            const int ng  = (nc + G - 1) / G;
            if (g >= gacc && g < gacc + ng) {
                const int gi = g - gacc;
                const int c0 = gi * G;
                gn        = min(G, nc - c0);
                chunk0    = cacc + c0;
                start_tok = s0 + c0 * st;
            }
            gacc += ng;
            cacc += nc;
        }
    }
    if (gn <= 0) return;

    const float inv = 1.0f / (float)ks;

    if (ks == KS_C && st == ST_C) {
        // ── Fast path ───────────────────────────────────────────────────
        // Pair i of half h = rows (2i, 2i+1); thread t reads floats
        // [t*8, t*8+8) of the 1KB pair: t<64 -> even row, t>=64 -> odd
        // row, d-slice d0 = (t&63)*8. All loads unconditional; the
        // (possibly unused) trailing half of a partial group is clamped
        // in-bounds and never combined into a stored chunk.
        float a[G + 1][8];
        #pragma unroll
        for (int h = 0; h <= G; h++) {
            int row0 = start_tok + h * ST_C;
            row0 = min(row0, T - ST_C);
            halfsum_v8(kf + (size_t)row0 * HD + tid * 8, a[h]);
        }

        // Exchange the cross-parity partials (single sync, at the end).
        const int u = tid & 63;
        if (tid < 64) {
            #pragma unroll
            for (int j = 0; j < 8; j++)
                sh[0][u][j] = a[1][j] + a[2][j];       // chunk1 even
        } else {
            #pragma unroll
            for (int j = 0; j < 8; j++)
                sh[1][u][j] = a[0][j] + a[1][j];       // chunk0 odd
        }
        __syncthreads();

        if (tid < 64) {
            // chunk0 = even(c0) + odd(c0)
            float4 o0, o1;
            float o[8];
            #pragma unroll
            for (int j = 0; j < 8; j++)
                o[j] = (a[0][j] + a[1][j] + sh[1][u][j]) * inv;
            o0 = make_float4(o[0], o[1], o[2], o[3]);
            o1 = make_float4(o[4], o[5], o[6], o[7]);
            float4* dst = (float4*)(out + (size_t)chunk0 * HD + u * 8);
            dst[0] = o0; dst[1] = o1;
        } else if (gn == 2) {
            // chunk1 = odd(c1) + even(c1)
            float o[8];
            #pragma unroll
            for (int j = 0; j < 8; j++)
                o[j] = (a[1][j] + a[2][j] + sh[0][u][j]) * inv;
            float4* dst = (float4*)(out + (size_t)(chunk0 + 1) * HD + u * 8);
            dst[0] = make_float4(o[0], o[1], o[2], o[3]);
            dst[1] = make_float4(o[4], o[5], o[6], o[7]);
        }
    } else {
        // ── Generic fallback: naive per-chunk float4 sums ───────────────
        const float4* k4 = (const float4*)kf;
        for (int h = 0; h < gn; h++) {
            const float4* p = k4 + (size_t)(start_tok + h * st) * HD4 + tid;
            float4 s = make_float4(0.f, 0.f, 0.f, 0.f);
            #pragma unroll 8
            for (int t = 0; t < ks; t++) {
                const float4 v = p[(size_t)t * HD4];
                s.x += v.x; s.y += v.y; s.z += v.z; s.w += v.w;
            }
            s.x *= inv; s.y *= inv; s.z *= inv; s.w *= inv;
            ((float4*)out)[(size_t)(chunk0 + h) * HD4 + tid] = s;
        }
    }
}

extern "C" void kernel_launch(void* const* d_in, const int* in_sizes, int n_in,
                              void* d_out, int out_size)
{
    const float* kf   = (const float*)d_in[0];
    const int*   cu   = (const int*)d_in[1];
    const int*   p_ks = (const int*)d_in[2];
    const int*   p_st = (const int*)d_in[3];

    const int B = in_sizes[1] - 1;

    // Chunk count from output size; remainder = appended compressed cu_seqlens.
    const int NC   = out_size / HD;
    const int tail = out_size - NC * HD;
    if (NC <= 0) return;

    // Upper bound on groups: ceil(NC/G) plus one partial group per sequence.
    const int max_groups = (NC + G - 1) / G + B;

    compressk_kernel<<<max_groups, BLK>>>(
        kf, cu, p_ks, p_st,
        (float*)d_out,
        (float*)d_out + (size_t)NC * HD,
        B, tail);
}